// round 11
// baseline (speedup 1.0000x reference)
#include <cuda_runtime.h>
#include <math.h>

// Problem constants
#define N_B    2
#define S_LEN  2048
#define T_LEN  2048
#define E_DIM  1024
#define H_NUM  16
#define HD     64
#define M_ROWS (N_B * S_LEN)   // 4096

// Scratch (device globals -> no runtime allocation)
__device__ float    g_q [M_ROWS * E_DIM];   // Q proj (tf32 bits)
__device__ float    g_k [M_ROWS * E_DIM];   // K proj (tf32 bits)
__device__ float    g_v [M_ROWS * E_DIM];   // V proj (tf32 bits)
__device__ float    g_ao[M_ROWS * E_DIM];   // attn out (tf32 bits)
__device__ unsigned g_qa[M_ROWS * E_DIM];   // query  activation (tf32 bits)
__device__ unsigned g_ka[M_ROWS * E_DIM];   // key    activation (tf32 bits)
__device__ unsigned g_va[M_ROWS * E_DIM];   // value  activation (tf32 bits)
__device__ unsigned g_wq[E_DIM * E_DIM];    // Wq (tf32 bits)
__device__ unsigned g_wk[E_DIM * E_DIM];    // Wk (tf32 bits)
__device__ unsigned g_wv[E_DIM * E_DIM];    // Wv (tf32 bits)
__device__ unsigned g_wo[E_DIM * E_DIM];    // Wo (tf32 bits)

// ---------------------------------------------------------------------------
// Helpers
// ---------------------------------------------------------------------------
__device__ __forceinline__ unsigned f2tf32(float f) {
    unsigned u;
    asm("cvt.rna.tf32.f32 %0, %1;" : "=r"(u) : "f"(f));
    return u;
}

__device__ __forceinline__ void mma_tf32(float* c, const unsigned* a, const unsigned* b) {
    asm volatile(
        "mma.sync.aligned.m16n8k8.row.col.f32.tf32.tf32.f32 "
        "{%0,%1,%2,%3}, {%4,%5,%6,%7}, {%8,%9}, {%0,%1,%2,%3};"
        : "+f"(c[0]), "+f"(c[1]), "+f"(c[2]), "+f"(c[3])
        : "r"(a[0]), "r"(a[1]), "r"(a[2]), "r"(a[3]), "r"(b[0]), "r"(b[1]));
}

__device__ __forceinline__ void cp16(void* dst_smem, const void* src_gmem) {
    unsigned d = (unsigned)__cvta_generic_to_shared(dst_smem);
    asm volatile("cp.async.ca.shared.global [%0], [%1], 16;" :: "r"(d), "l"(src_gmem));
}

// ---------------------------------------------------------------------------
// Conversion kernels: fp32 -> tf32 bits (RNA), vectorized. HBM-bound.
// ---------------------------------------------------------------------------
__global__ __launch_bounds__(256)
void cvt_act(const float* __restrict__ q, const float* __restrict__ k,
             const float* __restrict__ v,
             unsigned* __restrict__ qo, unsigned* __restrict__ ko,
             unsigned* __restrict__ vo)
{
    const int z = blockIdx.z;
    const float* src = (z == 0) ? q : (z == 1) ? k : v;
    unsigned*    dst = (z == 0) ? qo : (z == 1) ? ko : vo;
    int i = blockIdx.x * blockDim.x + threadIdx.x;      // float4 index
    float4 val = ((const float4*)src)[i];
    uint4 o;
    o.x = f2tf32(val.x);
    o.y = f2tf32(val.y);
    o.z = f2tf32(val.z);
    o.w = f2tf32(val.w);
    ((uint4*)dst)[i] = o;
}

__global__ __launch_bounds__(256)
void cvt_w(const float* __restrict__ wq, const float* __restrict__ wk,
           const float* __restrict__ wv, const float* __restrict__ wo,
           unsigned* __restrict__ oq, unsigned* __restrict__ ok,
           unsigned* __restrict__ ov, unsigned* __restrict__ oo)
{
    const int z = blockIdx.z;
    const float* src = (z == 0) ? wq : (z == 1) ? wk : (z == 2) ? wv : wo;
    unsigned*    dst = (z == 0) ? oq : (z == 1) ? ok : (z == 2) ? ov : oo;
    int i = blockIdx.x * blockDim.x + threadIdx.x;
    float4 val = ((const float4*)src)[i];
    uint4 o;
    o.x = f2tf32(val.x);
    o.y = f2tf32(val.y);
    o.z = f2tf32(val.z);
    o.w = f2tf32(val.w);
    ((uint4*)dst)[i] = o;
}

// ---------------------------------------------------------------------------
// GEMM (tf32 tensor core, cp.async 2-stage, NO cvt anywhere):
// C[M,1024] = (A[M,1024] @ W[1024,1024] + bias) * scale
// A, W are pre-converted tf32 bits. 128x128 CTA tile, BK=32, 256 threads.
// ---------------------------------------------------------------------------
#define ASTR 36
#define BSTR 136
#define AS_WORDS (128 * ASTR)          // 4608
#define BS_WORDS (32 * BSTR)           // 4352
#define GEMM_SMEM_WORDS (2 * (AS_WORDS + BS_WORDS))   // 17920
#define GEMM_SMEM_BYTES (GEMM_SMEM_WORDS * 4)         // 71680

__device__ __forceinline__
void gemm_load_tile(const unsigned* __restrict__ A, const unsigned* __restrict__ W,
                    int m0, int n0, int kt, unsigned* As, unsigned* Bs, int tid)
{
#pragma unroll
    for (int p = 0; p < 4; p++) {
        int f = tid + p * 256;
        int r = f >> 3;
        int c = (f & 7) << 2;
        cp16(As + r * ASTR + c, A + (size_t)(m0 + r) * E_DIM + kt + c);
    }
#pragma unroll
    for (int p = 0; p < 4; p++) {
        int f = tid + p * 256;
        int r = f >> 5;
        int c = (f & 31) << 2;
        cp16(Bs + r * BSTR + c, W + (size_t)(kt + r) * E_DIM + n0 + c);
    }
    asm volatile("cp.async.commit_group;");
}

__device__ __forceinline__
void gemm_body(const unsigned* __restrict__ A, const unsigned* __restrict__ W,
               const float* __restrict__ bias, float* __restrict__ C,
               float scale, int tf32_out, int m0, int n0, unsigned* sm)
{
    unsigned* As[2] = { sm,                 sm + AS_WORDS };
    unsigned* Bs[2] = { sm + 2 * AS_WORDS, sm + 2 * AS_WORDS + BS_WORDS };

    const int tid  = threadIdx.x;
    const int lane = tid & 31;
    const int w    = tid >> 5;
    const int wm   = (w >> 2) * 64;
    const int wn   = (w & 3) * 32;

    float acc[4][4][4];
#pragma unroll
    for (int mi = 0; mi < 4; mi++)
#pragma unroll
        for (int ni = 0; ni < 4; ni++)
#pragma unroll
            for (int c = 0; c < 4; c++) acc[mi][ni][c] = 0.f;

    gemm_load_tile(A, W, m0, n0, 0, As[0], Bs[0], tid);

    for (int it = 0; it < E_DIM / 32; it++) {
        if (it + 1 < E_DIM / 32) {
            gemm_load_tile(A, W, m0, n0, (it + 1) * 32,
                           As[(it + 1) & 1], Bs[(it + 1) & 1], tid);
            asm volatile("cp.async.wait_group 1;");
        } else {
            asm volatile("cp.async.wait_group 0;");
        }
        __syncthreads();

        const unsigned* Ab = As[it & 1];
        const unsigned* Bb = Bs[it & 1];
#pragma unroll
        for (int kk = 0; kk < 4; kk++) {
            const int kb = kk * 8;
            unsigned af[4][4];
#pragma unroll
            for (int mi = 0; mi < 4; mi++) {
                int rbase = wm + mi * 16 + (lane >> 2);
                int cbase = kb + (lane & 3);
                af[mi][0] = Ab[rbase * ASTR + cbase];
                af[mi][1] = Ab[(rbase + 8) * ASTR + cbase];
                af[mi][2] = Ab[rbase * ASTR + cbase + 4];
                af[mi][3] = Ab[(rbase + 8) * ASTR + cbase + 4];
            }
            unsigned bf[4][2];
#pragma unroll
            for (int ni = 0; ni < 4; ni++) {
                int kbase = kb + (lane & 3);
                int nbase = wn + ni * 8 + (lane >> 2);
                bf[ni][0] = Bb[kbase * BSTR + nbase];
                bf[ni][1] = Bb[(kbase + 4) * BSTR + nbase];
            }
#pragma unroll
            for (int mi = 0; mi < 4; mi++)
#pragma unroll
                for (int ni = 0; ni < 4; ni++)
                    mma_tf32(acc[mi][ni], af[mi], bf[ni]);
        }
        __syncthreads();
    }

#pragma unroll
    for (int mi = 0; mi < 4; mi++) {
#pragma unroll
        for (int ni = 0; ni < 4; ni++) {
            int row = m0 + wm + mi * 16 + (lane >> 2);
            int col = n0 + wn + ni * 8 + 2 * (lane & 3);
            float v00 = (acc[mi][ni][0] + bias[col])     * scale;
            float v01 = (acc[mi][ni][1] + bias[col + 1]) * scale;
            float v10 = (acc[mi][ni][2] + bias[col])     * scale;
            float v11 = (acc[mi][ni][3] + bias[col + 1]) * scale;
            float2 o0, o1;
            if (tf32_out) {
                o0.x = __uint_as_float(f2tf32(v00));
                o0.y = __uint_as_float(f2tf32(v01));
                o1.x = __uint_as_float(f2tf32(v10));
                o1.y = __uint_as_float(f2tf32(v11));
            } else {
                o0.x = v00; o0.y = v01; o1.x = v10; o1.y = v11;
            }
            *(float2*)(C + (size_t)row * E_DIM + col)       = o0;
            *(float2*)(C + (size_t)(row + 8) * E_DIM + col) = o1;
        }
    }
}

// Fused QKV projections: blockIdx.z selects operand set.
__global__ __launch_bounds__(256, 2)
void gemm_qkv(const unsigned* __restrict__ qa, const unsigned* __restrict__ ka,
              const unsigned* __restrict__ va,
              const unsigned* __restrict__ Wq, const float* __restrict__ bq,
              const unsigned* __restrict__ Wk, const float* __restrict__ bk,
              const unsigned* __restrict__ Wv, const float* __restrict__ bv,
              float* __restrict__ q_out, float* __restrict__ k_out,
              float* __restrict__ v_out)
{
    extern __shared__ unsigned smu[];
    const int z = blockIdx.z;
    const unsigned* A = (z == 0) ? qa : (z == 1) ? ka : va;
    const unsigned* W = (z == 0) ? Wq : (z == 1) ? Wk : Wv;
    const float*    b = (z == 0) ? bq : (z == 1) ? bk : bv;
    float*          C = (z == 0) ? q_out : (z == 1) ? k_out : v_out;
    float scale       = (z == 0) ? 0.125f : 1.0f;   // Q pre-scaled by 1/sqrt(HD)
    gemm_body(A, W, b, C, scale, 1, blockIdx.y * 128, blockIdx.x * 128, smu);
}

// Output projection (fp32 out).
__global__ __launch_bounds__(256, 2)
void gemm_out(const unsigned* __restrict__ A, const unsigned* __restrict__ W,
              const float* __restrict__ bias, float* __restrict__ C)
{
    extern __shared__ unsigned smu[];
    gemm_body(A, W, bias, C, 1.0f, 0, blockIdx.y * 128, blockIdx.x * 128, smu);
}

// ---------------------------------------------------------------------------
// Flash attention v3 (unchanged structure; epilogue now writes tf32 bits so
// the output projection can consume pre-converted input).
// CTA = 128 threads (4 warps) per (n, h, 128-query block). T tiled by 64.
// Warp w owns q rows 32w..32w+31 (two m16 tiles); b-fragments reused across
// both m tiles.
// Smem:
//   Qs[128][68] [q][d]  Ks[64][68] [t][d]  Ps[128][68] [q][t]  Vs[64][72] [t][d]
// ---------------------------------------------------------------------------
#define QSTR 68
#define VSTR 72
#define SM_Q  0
#define SM_K  (128 * QSTR)
#define SM_P  (SM_K + 64 * QSTR)
#define SM_V  (SM_P + 128 * QSTR)
#define SM_WORDS (SM_V + 64 * VSTR)     // 26368 words
#define SM_BYTES (SM_WORDS * 4)         // 105472 B

__global__ __launch_bounds__(128, 2)
void flash_attn_tc(const unsigned* __restrict__ Q, const unsigned* __restrict__ K,
                   const unsigned* __restrict__ V, float* __restrict__ O)
{
    extern __shared__ unsigned sm[];
    unsigned* Qs = sm + SM_Q;
    unsigned* Ks = sm + SM_K;
    unsigned* Ps = sm + SM_P;
    unsigned* Vs = sm + SM_V;

    const int tid   = threadIdx.x;
    const int lane  = tid & 31;
    const int w     = tid >> 5;
    const int qr    = lane >> 2;    // 0..7
    const int qc    = lane & 3;     // 0..3
    const int wbase = w * 32;

    const int qb = blockIdx.x;      // 0..15
    const int h  = blockIdx.y;
    const int n  = blockIdx.z;

    const unsigned* Qbase = Q + (size_t)(n * S_LEN + qb * 128) * E_DIM + h * HD;
    const unsigned* Kbase = K + (size_t)(n * T_LEN) * E_DIM + h * HD;
    const unsigned* Vbase = V + (size_t)(n * T_LEN) * E_DIM + h * HD;

    // Load Q tile (128x64) — already tf32 bits, pure copy
#pragma unroll
    for (int p = 0; p < 16; p++) {
        int f = tid + p * 128;        // 0..2047
        int r = f >> 4;               // 0..127
        int c = (f & 15) << 2;        // 0..60
        uint4 v = *(const uint4*)(Qbase + (size_t)r * E_DIM + c);
        Qs[r * QSTR + c + 0] = v.x;
        Qs[r * QSTR + c + 1] = v.y;
        Qs[r * QSTR + c + 2] = v.z;
        Qs[r * QSTR + c + 3] = v.w;
    }

    float oacc[2][8][4];
#pragma unroll
    for (int mi = 0; mi < 2; mi++)
#pragma unroll
        for (int nt = 0; nt < 8; nt++)
#pragma unroll
            for (int c = 0; c < 4; c++) oacc[mi][nt][c] = 0.f;
    float mrv[2][2], lrv[2][2];
#pragma unroll
    for (int mi = 0; mi < 2; mi++)
#pragma unroll
        for (int hf = 0; hf < 2; hf++) { mrv[mi][hf] = -1e30f; lrv[mi][hf] = 0.f; }

    for (int t0 = 0; t0 < T_LEN; t0 += 64) {
        // Load K and V tiles — pure copies
#pragma unroll
        for (int p = 0; p < 8; p++) {
            int f = tid + p * 128;
            int r = f >> 4;
            int c = (f & 15) << 2;
            uint4 kv = *(const uint4*)(Kbase + (size_t)(t0 + r) * E_DIM + c);
            Ks[r * QSTR + c + 0] = kv.x;
            Ks[r * QSTR + c + 1] = kv.y;
            Ks[r * QSTR + c + 2] = kv.z;
            Ks[r * QSTR + c + 3] = kv.w;
            uint4 vv = *(const uint4*)(Vbase + (size_t)(t0 + r) * E_DIM + c);
            *(uint4*)(Vs + r * VSTR + c) = vv;
        }
        __syncthreads();

        // ---- S = Q K^T ----
        float sacc[2][8][4];
#pragma unroll
        for (int mi = 0; mi < 2; mi++)
#pragma unroll
            for (int nt = 0; nt < 8; nt++)
#pragma unroll
                for (int c = 0; c < 4; c++) sacc[mi][nt][c] = 0.f;

#pragma unroll
        for (int kk = 0; kk < 8; kk++) {
            const int kb = kk * 8;
            unsigned a0[4], a1[4];
            int r0 = (wbase + qr) * QSTR + kb + qc;
            a0[0] = Qs[r0];
            a0[1] = Qs[r0 + 8 * QSTR];
            a0[2] = Qs[r0 + 4];
            a0[3] = Qs[r0 + 8 * QSTR + 4];
            int r1 = r0 + 16 * QSTR;
            a1[0] = Qs[r1];
            a1[1] = Qs[r1 + 8 * QSTR];
            a1[2] = Qs[r1 + 4];
            a1[3] = Qs[r1 + 8 * QSTR + 4];
#pragma unroll
            for (int nt = 0; nt < 8; nt++) {
                unsigned b[2];
                int bi = (nt * 8 + qr) * QSTR + kb + qc;
                b[0] = Ks[bi];
                b[1] = Ks[bi + 4];
                mma_tf32(sacc[0][nt], a0, b);
                mma_tf32(sacc[1][nt], a1, b);
            }
        }

        // ---- online softmax ----
#pragma unroll
        for (int mi = 0; mi < 2; mi++) {
#pragma unroll
            for (int hf = 0; hf < 2; hf++) {
                float mx = -1e30f;
#pragma unroll
                for (int nt = 0; nt < 8; nt++)
                    mx = fmaxf(mx, fmaxf(sacc[mi][nt][2 * hf], sacc[mi][nt][2 * hf + 1]));
                mx = fmaxf(mx, __shfl_xor_sync(0xffffffffu, mx, 1));
                mx = fmaxf(mx, __shfl_xor_sync(0xffffffffu, mx, 2));
                float mn = fmaxf(mrv[mi][hf], mx);
                float al = __expf(mrv[mi][hf] - mn);
                mrv[mi][hf] = mn;
                float ls = 0.f;
                int prow = (wbase + mi * 16 + qr + 8 * hf) * QSTR + 2 * qc;
#pragma unroll
                for (int nt = 0; nt < 8; nt++) {
                    float p0 = __expf(sacc[mi][nt][2 * hf]     - mn);
                    float p1 = __expf(sacc[mi][nt][2 * hf + 1] - mn);
                    ls += p0 + p1;
                    Ps[prow + nt * 8]     = f2tf32(p0);
                    Ps[prow + nt * 8 + 1] = f2tf32(p1);
                    oacc[mi][nt][2 * hf]     *= al;
                    oacc[mi][nt][2 * hf + 1] *= al;
                }
                ls += __shfl_xor_sync(0xffffffffu, ls, 1);
                ls += __shfl_xor_sync(0xffffffffu, ls, 2);
                lrv[mi][hf] = lrv[mi][hf] * al + ls;
            }
        }
        __syncwarp();   // P rows of this warp visible warp-wide

        // ---- O += P V ----
#pragma unroll
        for (int kk = 0; kk < 8; kk++) {
            const int kb = kk * 8;
            unsigned a0[4], a1[4];
            int r0 = (wbase + qr) * QSTR + kb + qc;
            a0[0] = Ps[r0];
            a0[1] = Ps[r0 + 8 * QSTR];
            a0[2] = Ps[r0 + 4];
            a0[3] = Ps[r0 + 8 * QSTR + 4];
            int r1 = r0 + 16 * QSTR;
            a1[0] = Ps[r1];
            a1[1] = Ps[r1 + 8 * QSTR];
            a1[2] = Ps[r1 + 4];
            a1[3] = Ps[r1 + 8 * QSTR + 4];
#pragma unroll
            for (int nt = 0; nt < 8; nt++) {
                unsigned b[2];
                int bi = (kb + qc) * VSTR + nt * 8 + qr;
                b[0] = Vs[bi];
                b[1] = Vs[bi + 4 * VSTR];
                mma_tf32(oacc[0][nt], a0, b);
                mma_tf32(oacc[1][nt], a1, b);
            }
        }
        __syncthreads();   // Ks/Vs consumed; safe to overwrite next iter
    }

    // Normalize and write out as tf32 bits (input to output projection)
#pragma unroll
    for (int mi = 0; mi < 2; mi++) {
        float inv0 = 1.f / lrv[mi][0];
        float inv1 = 1.f / lrv[mi][1];
        int grow0 = n * S_LEN + qb * 128 + wbase + mi * 16 + qr;
        int gcol  = h * HD + 2 * qc;
#pragma unroll
        for (int nt = 0; nt < 8; nt++) {
            float2 o0, o1;
            o0.x = __uint_as_float(f2tf32(oacc[mi][nt][0] * inv0));
            o0.y = __uint_as_float(f2tf32(oacc[mi][nt][1] * inv0));
            o1.x = __uint_as_float(f2tf32(oacc[mi][nt][2] * inv1));
            o1.y = __uint_as_float(f2tf32(oacc[mi][nt][3] * inv1));
            *(float2*)(O + (size_t)grow0 * E_DIM + gcol + nt * 8)       = o0;
            *(float2*)(O + (size_t)(grow0 + 8) * E_DIM + gcol + nt * 8) = o1;
        }
    }
}

// ---------------------------------------------------------------------------
// Launch
// ---------------------------------------------------------------------------
extern "C" void kernel_launch(void* const* d_in, const int* in_sizes, int n_in,
                              void* d_out, int out_size)
{
    const float* query = (const float*)d_in[0];
    const float* key   = (const float*)d_in[1];
    const float* value = (const float*)d_in[2];
    const float* Wq    = (const float*)d_in[3];
    const float* bq    = (const float*)d_in[4];
    const float* Wk    = (const float*)d_in[5];
    const float* bk    = (const float*)d_in[6];
    const float* Wv    = (const float*)d_in[7];
    const float* bv    = (const float*)d_in[8];
    const float* Wo    = (const float*)d_in[9];
    const float* bo    = (const float*)d_in[10];
    float* out = (float*)d_out;

    float *q_p, *k_p, *v_p, *ao_p;
    unsigned *qa_p, *ka_p, *va_p, *wq_p, *wk_p, *wv_p, *wo_p;
    cudaGetSymbolAddress((void**)&q_p,  g_q);
    cudaGetSymbolAddress((void**)&k_p,  g_k);
    cudaGetSymbolAddress((void**)&v_p,  g_v);
    cudaGetSymbolAddress((void**)&ao_p, g_ao);
    cudaGetSymbolAddress((void**)&qa_p, g_qa);
    cudaGetSymbolAddress((void**)&ka_p, g_ka);
    cudaGetSymbolAddress((void**)&va_p, g_va);
    cudaGetSymbolAddress((void**)&wq_p, g_wq);
    cudaGetSymbolAddress((void**)&wk_p, g_wk);
    cudaGetSymbolAddress((void**)&wv_p, g_wv);
    cudaGetSymbolAddress((void**)&wo_p, g_wo);

    static int configured = 0;
    if (!configured) {
        cudaFuncSetAttribute(gemm_qkv,
                             cudaFuncAttributeMaxDynamicSharedMemorySize, GEMM_SMEM_BYTES);
        cudaFuncSetAttribute(gemm_out,
                             cudaFuncAttributeMaxDynamicSharedMemorySize, GEMM_SMEM_BYTES);
        cudaFuncSetAttribute(flash_attn_tc,
                             cudaFuncAttributeMaxDynamicSharedMemorySize, SM_BYTES);
        cudaFuncSetAttribute(flash_attn_tc,
                             cudaFuncAttributePreferredSharedMemoryCarveout, 100);
        configured = 1;
    }

    // Pre-convert activations and weights to tf32 bits (HBM-bound, ~25 us)
    dim3 act_grid(M_ROWS * E_DIM / 4 / 256, 1, 3);   // 4096 x 1 x 3
    cvt_act<<<act_grid, 256>>>(query, key, value, qa_p, ka_p, va_p);
    dim3 w_grid(E_DIM * E_DIM / 4 / 256, 1, 4);      // 1024 x 1 x 4
    cvt_w<<<w_grid, 256>>>(Wq, Wk, Wv, Wo, wq_p, wk_p, wv_p, wo_p);

    // Fused QKV projections (z = 0,1,2), cp.async double-buffered
    dim3 qkv_grid(E_DIM / 128, M_ROWS / 128, 3);     // 8 x 32 x 3
    gemm_qkv<<<qkv_grid, 256, GEMM_SMEM_BYTES>>>(qa_p, ka_p, va_p,
                                                 wq_p, bq, wk_p, bk, wv_p, bv,
                                                 q_p, k_p, v_p);

    // Flash attention (q-tile 128)
    dim3 attn_grid(S_LEN / 128, H_NUM, N_B);         // 16 x 16 x 2
    flash_attn_tc<<<attn_grid, 128, SM_BYTES>>>(
        (const unsigned*)q_p, (const unsigned*)k_p, (const unsigned*)v_p, ao_p);

    // Output projection (ao is tf32 bits from flash epilogue)
    dim3 gemm_grid(E_DIM / 128, M_ROWS / 128);       // 8 x 32
    gemm_out<<<gemm_grid, 256, GEMM_SMEM_BYTES>>>(
        (const unsigned*)ao_p, wo_p, bo, out);
}

// round 14
// speedup vs baseline: 1.0366x; 1.0366x over previous
#include <cuda_runtime.h>
#include <math.h>

// Problem constants
#define N_B    2
#define S_LEN  2048
#define T_LEN  2048
#define E_DIM  1024
#define H_NUM  16
#define HD     64
#define M_ROWS (N_B * S_LEN)   // 4096

// Scratch (device globals -> no runtime allocation)
__device__ float g_q [M_ROWS * E_DIM];   // tf32 bit patterns
__device__ float g_k [M_ROWS * E_DIM];   // tf32 bit patterns
__device__ float g_v [M_ROWS * E_DIM];   // tf32 bit patterns
__device__ float g_ao[M_ROWS * E_DIM];   // fp32

// ---------------------------------------------------------------------------
// Helpers
// ---------------------------------------------------------------------------
__device__ __forceinline__ unsigned f2tf32(float f) {
    unsigned u;
    asm("cvt.rna.tf32.f32 %0, %1;" : "=r"(u) : "f"(f));
    return u;
}

__device__ __forceinline__ void mma_tf32(float* c, const unsigned* a, const unsigned* b) {
    asm volatile(
        "mma.sync.aligned.m16n8k8.row.col.f32.tf32.tf32.f32 "
        "{%0,%1,%2,%3}, {%4,%5,%6,%7}, {%8,%9}, {%0,%1,%2,%3};"
        : "+f"(c[0]), "+f"(c[1]), "+f"(c[2]), "+f"(c[3])
        : "r"(a[0]), "r"(a[1]), "r"(a[2]), "r"(a[3]), "r"(b[0]), "r"(b[1]));
}

// ---------------------------------------------------------------------------
// GEMM (tf32 tensor core, BK=64): C = (A @ W + bias) * scale
// 128x128 CTA tile, BK=64, 256 threads = 8 warps (2x4), warp tile 64x32.
// cvt.rna at tile fill (R9-identical arithmetic); single-buffered; the 2
// resident CTAs/SM overlap each other's fill/mma phases. BK=64 halves the
// barrier count and doubles fill MLP vs BK=32.
// ---------------------------------------------------------------------------
#define ASTR 68
#define BSTR 136
#define AS_WORDS (128 * ASTR)                 // 8704
#define BS_WORDS (64 * BSTR)                  // 8704
#define GEMM_SMEM_BYTES ((AS_WORDS + BS_WORDS) * 4)   // 69632

__device__ __forceinline__
void gemm_body(const float* __restrict__ A, const float* __restrict__ W,
               const float* __restrict__ bias, float* __restrict__ C,
               float scale, int tf32_out, int m0, int n0, unsigned* sm)
{
    unsigned* As = sm;              // As[m][k], stride 68
    unsigned* Bs = sm + AS_WORDS;   // Bs[k][n], stride 136

    const int tid  = threadIdx.x;
    const int lane = tid & 31;
    const int w    = tid >> 5;
    const int wm   = (w >> 2) * 64;
    const int wn   = (w & 3) * 32;

    float acc[4][4][4];
#pragma unroll
    for (int mi = 0; mi < 4; mi++)
#pragma unroll
        for (int ni = 0; ni < 4; ni++)
#pragma unroll
            for (int c = 0; c < 4; c++) acc[mi][ni][c] = 0.f;

    for (int kt = 0; kt < E_DIM; kt += 64) {
        // A tile 128x64
#pragma unroll
        for (int p = 0; p < 8; p++) {
            int f = tid + p * 256;            // 0..2047
            int r = f >> 4;                   // 0..127
            int c = (f & 15) << 2;            // 0..60
            float4 v = *(const float4*)(A + (size_t)(m0 + r) * E_DIM + kt + c);
            As[r * ASTR + c + 0] = f2tf32(v.x);
            As[r * ASTR + c + 1] = f2tf32(v.y);
            As[r * ASTR + c + 2] = f2tf32(v.z);
            As[r * ASTR + c + 3] = f2tf32(v.w);
        }
        // B tile 64x128
#pragma unroll
        for (int p = 0; p < 8; p++) {
            int f = tid + p * 256;            // 0..2047
            int r = f >> 5;                   // 0..63
            int c = (f & 31) << 2;            // 0..124
            float4 v = *(const float4*)(W + (size_t)(kt + r) * E_DIM + n0 + c);
            Bs[r * BSTR + c + 0] = f2tf32(v.x);
            Bs[r * BSTR + c + 1] = f2tf32(v.y);
            Bs[r * BSTR + c + 2] = f2tf32(v.z);
            Bs[r * BSTR + c + 3] = f2tf32(v.w);
        }
        __syncthreads();

#pragma unroll
        for (int kk = 0; kk < 8; kk++) {
            const int kb = kk * 8;
            unsigned af[4][4];
#pragma unroll
            for (int mi = 0; mi < 4; mi++) {
                int rbase = wm + mi * 16 + (lane >> 2);
                int cbase = kb + (lane & 3);
                af[mi][0] = As[rbase * ASTR + cbase];
                af[mi][1] = As[(rbase + 8) * ASTR + cbase];
                af[mi][2] = As[rbase * ASTR + cbase + 4];
                af[mi][3] = As[(rbase + 8) * ASTR + cbase + 4];
            }
            unsigned bf[4][2];
#pragma unroll
            for (int ni = 0; ni < 4; ni++) {
                int kbase = kb + (lane & 3);
                int nbase = wn + ni * 8 + (lane >> 2);
                bf[ni][0] = Bs[kbase * BSTR + nbase];
                bf[ni][1] = Bs[(kbase + 4) * BSTR + nbase];
            }
#pragma unroll
            for (int mi = 0; mi < 4; mi++)
#pragma unroll
                for (int ni = 0; ni < 4; ni++)
                    mma_tf32(acc[mi][ni], af[mi], bf[ni]);
        }
        __syncthreads();
    }

#pragma unroll
    for (int mi = 0; mi < 4; mi++) {
#pragma unroll
        for (int ni = 0; ni < 4; ni++) {
            int row = m0 + wm + mi * 16 + (lane >> 2);
            int col = n0 + wn + ni * 8 + 2 * (lane & 3);
            float v00 = (acc[mi][ni][0] + bias[col])     * scale;
            float v01 = (acc[mi][ni][1] + bias[col + 1]) * scale;
            float v10 = (acc[mi][ni][2] + bias[col])     * scale;
            float v11 = (acc[mi][ni][3] + bias[col + 1]) * scale;
            float2 o0, o1;
            if (tf32_out) {
                o0.x = __uint_as_float(f2tf32(v00));
                o0.y = __uint_as_float(f2tf32(v01));
                o1.x = __uint_as_float(f2tf32(v10));
                o1.y = __uint_as_float(f2tf32(v11));
            } else {
                o0.x = v00; o0.y = v01; o1.x = v10; o1.y = v11;
            }
            *(float2*)(C + (size_t)row * E_DIM + col)       = o0;
            *(float2*)(C + (size_t)(row + 8) * E_DIM + col) = o1;
        }
    }
}

// Fused QKV projections: blockIdx.z selects operand set.
__global__ __launch_bounds__(256, 2)
void gemm_qkv(const float* __restrict__ query, const float* __restrict__ key,
              const float* __restrict__ value,
              const float* __restrict__ Wq, const float* __restrict__ bq,
              const float* __restrict__ Wk, const float* __restrict__ bk,
              const float* __restrict__ Wv, const float* __restrict__ bv,
              float* __restrict__ q_out, float* __restrict__ k_out,
              float* __restrict__ v_out)
{
    extern __shared__ unsigned smu[];
    const int z = blockIdx.z;
    const float* A = (z == 0) ? query : (z == 1) ? key : value;
    const float* W = (z == 0) ? Wq    : (z == 1) ? Wk  : Wv;
    const float* b = (z == 0) ? bq    : (z == 1) ? bk  : bv;
    float*       C = (z == 0) ? q_out : (z == 1) ? k_out : v_out;
    float scale    = (z == 0) ? 0.125f : 1.0f;   // Q pre-scaled by 1/sqrt(HD)
    gemm_body(A, W, b, C, scale, 1, blockIdx.y * 128, blockIdx.x * 128, smu);
}

// Output projection (fp32 out).
__global__ __launch_bounds__(256, 2)
void gemm_tc(const float* __restrict__ A, const float* __restrict__ W,
             const float* __restrict__ bias, float* __restrict__ C,
             float scale, int tf32_out)
{
    extern __shared__ unsigned smu[];
    gemm_body(A, W, bias, C, scale, tf32_out,
              blockIdx.y * 128, blockIdx.x * 128, smu);
}

// ---------------------------------------------------------------------------
// Flash attention v3 (exact R9 form — measured ~290 us; untouched).
// CTA = 128 threads (4 warps) per (n, h, 128-query block). T tiled by 64.
// Warp w owns q rows 32w..32w+31 (two m16 tiles); b-fragments reused across
// both m tiles.
// Smem:
//   Qs[128][68] [q][d]  Ks[64][68] [t][d]  Ps[128][68] [q][t]  Vs[64][72] [t][d]
// ---------------------------------------------------------------------------
#define QSTR 68
#define VSTR 72
#define SM_Q  0
#define SM_K  (128 * QSTR)
#define SM_P  (SM_K + 64 * QSTR)
#define SM_V  (SM_P + 128 * QSTR)
#define SM_WORDS (SM_V + 64 * VSTR)     // 26368 words
#define SM_BYTES (SM_WORDS * 4)         // 105472 B

__global__ __launch_bounds__(128, 2)
void flash_attn_tc(const unsigned* __restrict__ Q, const unsigned* __restrict__ K,
                   const unsigned* __restrict__ V, float* __restrict__ O)
{
    extern __shared__ unsigned sm[];
    unsigned* Qs = sm + SM_Q;
    unsigned* Ks = sm + SM_K;
    unsigned* Ps = sm + SM_P;
    unsigned* Vs = sm + SM_V;

    const int tid   = threadIdx.x;
    const int lane  = tid & 31;
    const int w     = tid >> 5;
    const int qr    = lane >> 2;    // 0..7
    const int qc    = lane & 3;     // 0..3
    const int wbase = w * 32;

    const int qb = blockIdx.x;      // 0..15
    const int h  = blockIdx.y;
    const int n  = blockIdx.z;

    const unsigned* Qbase = Q + (size_t)(n * S_LEN + qb * 128) * E_DIM + h * HD;
    const unsigned* Kbase = K + (size_t)(n * T_LEN) * E_DIM + h * HD;
    const unsigned* Vbase = V + (size_t)(n * T_LEN) * E_DIM + h * HD;

    // Load Q tile (128x64) — already tf32 bits, pure copy
#pragma unroll
    for (int p = 0; p < 16; p++) {
        int f = tid + p * 128;        // 0..2047
        int r = f >> 4;               // 0..127
        int c = (f & 15) << 2;        // 0..60
        uint4 v = *(const uint4*)(Qbase + (size_t)r * E_DIM + c);
        Qs[r * QSTR + c + 0] = v.x;
        Qs[r * QSTR + c + 1] = v.y;
        Qs[r * QSTR + c + 2] = v.z;
        Qs[r * QSTR + c + 3] = v.w;
    }

    float oacc[2][8][4];
#pragma unroll
    for (int mi = 0; mi < 2; mi++)
#pragma unroll
        for (int nt = 0; nt < 8; nt++)
#pragma unroll
            for (int c = 0; c < 4; c++) oacc[mi][nt][c] = 0.f;
    float mrv[2][2], lrv[2][2];
#pragma unroll
    for (int mi = 0; mi < 2; mi++)
#pragma unroll
        for (int hf = 0; hf < 2; hf++) { mrv[mi][hf] = -1e30f; lrv[mi][hf] = 0.f; }

    for (int t0 = 0; t0 < T_LEN; t0 += 64) {
        // Load K and V tiles — pure copies
#pragma unroll
        for (int p = 0; p < 8; p++) {
            int f = tid + p * 128;
            int r = f >> 4;
            int c = (f & 15) << 2;
            uint4 kv = *(const uint4*)(Kbase + (size_t)(t0 + r) * E_DIM + c);
            Ks[r * QSTR + c + 0] = kv.x;
            Ks[r * QSTR + c + 1] = kv.y;
            Ks[r * QSTR + c + 2] = kv.z;
            Ks[r * QSTR + c + 3] = kv.w;
            uint4 vv = *(const uint4*)(Vbase + (size_t)(t0 + r) * E_DIM + c);
            *(uint4*)(Vs + r * VSTR + c) = vv;
        }
        __syncthreads();

        // ---- S = Q K^T ----
        float sacc[2][8][4];
#pragma unroll
        for (int mi = 0; mi < 2; mi++)
#pragma unroll
            for (int nt = 0; nt < 8; nt++)
#pragma unroll
                for (int c = 0; c < 4; c++) sacc[mi][nt][c] = 0.f;

#pragma unroll
        for (int kk = 0; kk < 8; kk++) {
            const int kb = kk * 8;
            unsigned a0[4], a1[4];
            int r0 = (wbase + qr) * QSTR + kb + qc;
            a0[0] = Qs[r0];
            a0[1] = Qs[r0 + 8 * QSTR];
            a0[2] = Qs[r0 + 4];
            a0[3] = Qs[r0 + 8 * QSTR + 4];
            int r1 = r0 + 16 * QSTR;
            a1[0] = Qs[r1];
            a1[1] = Qs[r1 + 8 * QSTR];
            a1[2] = Qs[r1 + 4];
            a1[3] = Qs[r1 + 8 * QSTR + 4];
#pragma unroll
            for (int nt = 0; nt < 8; nt++) {
                unsigned b[2];
                int bi = (nt * 8 + qr) * QSTR + kb + qc;
                b[0] = Ks[bi];
                b[1] = Ks[bi + 4];
                mma_tf32(sacc[0][nt], a0, b);
                mma_tf32(sacc[1][nt], a1, b);
            }
        }

        // ---- online softmax ----
#pragma unroll
        for (int mi = 0; mi < 2; mi++) {
#pragma unroll
            for (int hf = 0; hf < 2; hf++) {
                float mx = -1e30f;
#pragma unroll
                for (int nt = 0; nt < 8; nt++)
                    mx = fmaxf(mx, fmaxf(sacc[mi][nt][2 * hf], sacc[mi][nt][2 * hf + 1]));
                mx = fmaxf(mx, __shfl_xor_sync(0xffffffffu, mx, 1));
                mx = fmaxf(mx, __shfl_xor_sync(0xffffffffu, mx, 2));
                float mn = fmaxf(mrv[mi][hf], mx);
                float al = __expf(mrv[mi][hf] - mn);
                mrv[mi][hf] = mn;
                float ls = 0.f;
                int prow = (wbase + mi * 16 + qr + 8 * hf) * QSTR + 2 * qc;
#pragma unroll
                for (int nt = 0; nt < 8; nt++) {
                    float p0 = __expf(sacc[mi][nt][2 * hf]     - mn);
                    float p1 = __expf(sacc[mi][nt][2 * hf + 1] - mn);
                    ls += p0 + p1;
                    Ps[prow + nt * 8]     = f2tf32(p0);
                    Ps[prow + nt * 8 + 1] = f2tf32(p1);
                    oacc[mi][nt][2 * hf]     *= al;
                    oacc[mi][nt][2 * hf + 1] *= al;
                }
                ls += __shfl_xor_sync(0xffffffffu, ls, 1);
                ls += __shfl_xor_sync(0xffffffffu, ls, 2);
                lrv[mi][hf] = lrv[mi][hf] * al + ls;
            }
        }
        __syncwarp();   // P rows of this warp visible warp-wide

        // ---- O += P V ----
#pragma unroll
        for (int kk = 0; kk < 8; kk++) {
            const int kb = kk * 8;
            unsigned a0[4], a1[4];
            int r0 = (wbase + qr) * QSTR + kb + qc;
            a0[0] = Ps[r0];
            a0[1] = Ps[r0 + 8 * QSTR];
            a0[2] = Ps[r0 + 4];
            a0[3] = Ps[r0 + 8 * QSTR + 4];
            int r1 = r0 + 16 * QSTR;
            a1[0] = Ps[r1];
            a1[1] = Ps[r1 + 8 * QSTR];
            a1[2] = Ps[r1 + 4];
            a1[3] = Ps[r1 + 8 * QSTR + 4];
#pragma unroll
            for (int nt = 0; nt < 8; nt++) {
                unsigned b[2];
                int bi = (kb + qc) * VSTR + nt * 8 + qr;
                b[0] = Vs[bi];
                b[1] = Vs[bi + 4 * VSTR];
                mma_tf32(oacc[0][nt], a0, b);
                mma_tf32(oacc[1][nt], a1, b);
            }
        }
        __syncthreads();   // Ks/Vs consumed; safe to overwrite next iter
    }

    // Normalize and write out: O[n*S + qb*128 + row][h*64 + col]
#pragma unroll
    for (int mi = 0; mi < 2; mi++) {
        float inv0 = 1.f / lrv[mi][0];
        float inv1 = 1.f / lrv[mi][1];
        int grow0 = n * S_LEN + qb * 128 + wbase + mi * 16 + qr;
        int gcol  = h * HD + 2 * qc;
#pragma unroll
        for (int nt = 0; nt < 8; nt++) {
            float2 o0, o1;
            o0.x = oacc[mi][nt][0] * inv0;
            o0.y = oacc[mi][nt][1] * inv0;
            o1.x = oacc[mi][nt][2] * inv1;
            o1.y = oacc[mi][nt][3] * inv1;
            *(float2*)(O + (size_t)grow0 * E_DIM + gcol + nt * 8)       = o0;
            *(float2*)(O + (size_t)(grow0 + 8) * E_DIM + gcol + nt * 8) = o1;
        }
    }
}

// ---------------------------------------------------------------------------
// Launch
// ---------------------------------------------------------------------------
extern "C" void kernel_launch(void* const* d_in, const int* in_sizes, int n_in,
                              void* d_out, int out_size)
{
    const float* query = (const float*)d_in[0];
    const float* key   = (const float*)d_in[1];
    const float* value = (const float*)d_in[2];
    const float* Wq    = (const float*)d_in[3];
    const float* bq    = (const float*)d_in[4];
    const float* Wk    = (const float*)d_in[5];
    const float* bk    = (const float*)d_in[6];
    const float* Wv    = (const float*)d_in[7];
    const float* bv    = (const float*)d_in[8];
    const float* Wo    = (const float*)d_in[9];
    const float* bo    = (const float*)d_in[10];
    float* out = (float*)d_out;

    float *q_p, *k_p, *v_p, *ao_p;
    cudaGetSymbolAddress((void**)&q_p,  g_q);
    cudaGetSymbolAddress((void**)&k_p,  g_k);
    cudaGetSymbolAddress((void**)&v_p,  g_v);
    cudaGetSymbolAddress((void**)&ao_p, g_ao);

    static int configured = 0;
    if (!configured) {
        cudaFuncSetAttribute(gemm_qkv,
                             cudaFuncAttributeMaxDynamicSharedMemorySize, GEMM_SMEM_BYTES);
        cudaFuncSetAttribute(gemm_tc,
                             cudaFuncAttributeMaxDynamicSharedMemorySize, GEMM_SMEM_BYTES);
        cudaFuncSetAttribute(flash_attn_tc,
                             cudaFuncAttributeMaxDynamicSharedMemorySize, SM_BYTES);
        cudaFuncSetAttribute(flash_attn_tc,
                             cudaFuncAttributePreferredSharedMemoryCarveout, 100);
        configured = 1;
    }

    // Fused QKV projections (z = 0,1,2), BK=64
    dim3 qkv_grid(E_DIM / 128, M_ROWS / 128, 3);   // 8 x 32 x 3
    gemm_qkv<<<qkv_grid, 256, GEMM_SMEM_BYTES>>>(query, key, value,
                                                 Wq, bq, Wk, bk, Wv, bv,
                                                 q_p, k_p, v_p);

    // Flash attention (q-tile 128)
    dim3 attn_grid(S_LEN / 128, H_NUM, N_B);       // 16 x 16 x 2
    flash_attn_tc<<<attn_grid, 128, SM_BYTES>>>(
        (const unsigned*)q_p, (const unsigned*)k_p, (const unsigned*)v_p, ao_p);

    // Output projection
    dim3 gemm_grid(E_DIM / 128, M_ROWS / 128);     // 8 x 32
    gemm_tc<<<gemm_grid, 256, GEMM_SMEM_BYTES>>>(ao_p, Wo, bo, out, 1.0f, 0);
}